// round 10
// baseline (speedup 1.0000x reference)
#include <cuda_runtime.h>

#define NN 14      // nodes per graph
#define NH 4       // heads
#define NC 64      // per-head channels
#define NO 256     // NH*NC
#define FIN 128
#define NEG 0.2f
#define MAXE 200   // >= E + NN = 196

typedef unsigned long long ull;
typedef unsigned int uint;

__device__ __forceinline__ ull pk2(float x, float y) {
    ull r; asm("mov.b64 %0, {%1, %2};" : "=l"(r) : "f"(x), "f"(y)); return r;
}
__device__ __forceinline__ ull fma2(ull a, ull b, ull c) {
    ull d; asm("fma.rn.f32x2 %0, %1, %2, %3;" : "=l"(d) : "l"(a), "l"(b), "l"(c)); return d;
}
__device__ __forceinline__ ull add2(ull a, ull b) {
    ull d; asm("add.rn.f32x2 %0, %1, %2;" : "=l"(d) : "l"(a), "l"(b)); return d;
}
__device__ __forceinline__ float to_tf32(float x) {
    uint u; asm("cvt.rna.tf32.f32 %0, %1;" : "=r"(u) : "f"(x));
    return __uint_as_float(u);
}
// D(16x8,f32) += A(16x8,tf32) @ B(8x8,tf32)
__device__ __forceinline__ void mma_tf32(float4& d, uint a0, uint a1, uint a2, uint a3,
                                         uint b0, uint b1) {
    asm("mma.sync.aligned.m16n8k8.row.col.f32.tf32.tf32.f32 "
        "{%0,%1,%2,%3}, {%4,%5,%6,%7}, {%8,%9}, {%0,%1,%2,%3};"
        : "+f"(d.x), "+f"(d.y), "+f"(d.z), "+f"(d.w)
        : "r"(a0), "r"(a1), "r"(a2), "r"(a3), "r"(b0), "r"(b1));
}

// ---- precomputed weights ----
// B-fragment-major: g_Wf[(kt*32 + j)*32 + lane] = {W[kt*8 + lane%4][j*8 + lane/4],
//                                                  W[kt*8 + lane%4 + 4][j*8 + lane/4]}  (tf32)
__device__ float2 g_W1f[16 * 32 * 32];
__device__ float2 g_W2f[8 * 32 * 32];
// a-vecs in D-fragment layout: j = half*16+nt, h = 2*half + (nt>>3),
// c = (nt&7)*8 + 2*(lane&3): {as[h][c], as[h][c+1], ad[h][c], ad[h][c+1]}
__device__ float4 g_af1[32 * 32];
__device__ float4 g_af2[32 * 32];
__device__ float  g_wfused[NN * NC];   // W_lin @ W_pred
__device__ float  g_bfused;
__device__ int    g_is64;

__global__ void prep_kernel(const float* __restrict__ W1, const float* __restrict__ as1,
                            const float* __restrict__ ad1,
                            const float* __restrict__ W2, const float* __restrict__ as2,
                            const float* __restrict__ ad2,
                            const float* __restrict__ Wlin, const float* __restrict__ blin,
                            const float* __restrict__ Wpred, const float* __restrict__ bpred,
                            const int* __restrict__ edges)
{
    int tid = blockIdx.x * blockDim.x + threadIdx.x;
    int nt  = gridDim.x * blockDim.x;

    for (int i = tid; i < 16*32*32; i += nt) {
        int kt = i >> 10, r = i & 1023, j = r >> 5, lane = r & 31;
        int k0 = kt*8 + (lane & 3), n = j*8 + (lane >> 2);
        g_W1f[i] = make_float2(to_tf32(W1[k0*NO + n]), to_tf32(W1[(k0+4)*NO + n]));
    }
    for (int i = tid; i < 8*32*32; i += nt) {
        int kt = i >> 10, r = i & 1023, j = r >> 5, lane = r & 31;
        int k0 = kt*8 + (lane & 3), n = j*8 + (lane >> 2);
        g_W2f[i] = make_float2(to_tf32(W2[k0*NO + n]), to_tf32(W2[(k0+4)*NO + n]));
    }
    for (int i = tid; i < 32*32; i += nt) {
        int j = i >> 5, lane = i & 31;
        int half = j >> 4, ntile = j & 15;
        int h = 2*half + (ntile >> 3);
        int c = (ntile & 7)*8 + 2*(lane & 3);
        g_af1[i] = make_float4(as1[h*NC + c], as1[h*NC + c + 1],
                               ad1[h*NC + c], ad1[h*NC + c + 1]);
        g_af2[i] = make_float4(as2[h*NC + c], as2[h*NC + c + 1],
                               ad2[h*NC + c], ad2[h*NC + c + 1]);
    }
    for (int i = tid; i < NN * NC; i += nt) {
        float s = 0.f;
        #pragma unroll
        for (int j = 0; j < NC/2; j++) s = fmaf(Wlin[i*(NC/2) + j], Wpred[j], s);
        g_wfused[i] = s;
    }
    if (tid == 0) {
        float s = bpred[0];
        #pragma unroll
        for (int j = 0; j < NC/2; j++) s = fmaf(blin[j], Wpred[j], s);
        g_bfused = s;
        int any = 0;
        #pragma unroll
        for (int k = 1; k < 256; k += 2) any |= edges[k];
        g_is64 = (any == 0) ? 1 : 0;
    }
}

// One GAT layer for one graph (2-warp CTA; this warp owns half = cols 128h..128h+127,
// heads 2h, 2h+1). Input xa [16 rows, stride XST floats] (tf32-rounded).
// Output (head mean + bias (+relu) (+tf32 cvt)) -> x2_sm [16][68].
template<int KT, int XST, bool RELU, bool CVT>
__device__ __forceinline__ void gat_layer(
    const float2* __restrict__ Wf, const float4* __restrict__ af,
    const float* __restrict__ bias,
    const float* xa, float* h_sm, float* x2_sm, float* M_w, float* alj,
    ull* part, const unsigned char* srcS, const int* off,
    int t, int lane, int half)
{
    const int r = lane >> 2, q = lane & 3;

    // zero this warp's M region (2 heads x 14 x 14)
    {
        float* Mz = M_w + half*392;
        for (int i = lane; i < 392; i += 32) Mz[i] = 0.f;
    }

    // ---- GEMM via tf32 mma: D[nt] = x(16xK) @ W(Kx8) for 16 n-tiles ----
    float4 D[16];
    #pragma unroll
    for (int nt = 0; nt < 16; nt++) D[nt] = make_float4(0.f, 0.f, 0.f, 0.f);

    const float2* wp = Wf + (half*16)*32 + lane;
    #pragma unroll 1
    for (int kt = 0; kt < KT; kt++) {
        uint a0 = __float_as_uint(xa[r*XST + kt*8 + q]);
        uint a1 = __float_as_uint(xa[(r+8)*XST + kt*8 + q]);
        uint a2 = __float_as_uint(xa[r*XST + kt*8 + q + 4]);
        uint a3 = __float_as_uint(xa[(r+8)*XST + kt*8 + q + 4]);
        #pragma unroll
        for (int nt = 0; nt < 16; nt++) {
            float2 b = wp[kt*1024 + nt*32];
            mma_tf32(D[nt], a0, a1, a2, a3,
                     __float_as_uint(b.x), __float_as_uint(b.y));
        }
    }

    // ---- attention logits from D fragments ----
    {
        float ss[2][2] = {{0.f,0.f},{0.f,0.f}};   // [head-sel][row-sel]
        float sd[2][2] = {{0.f,0.f},{0.f,0.f}};
        const float4* afp = af + (half*16)*32 + lane;
        #pragma unroll
        for (int nt = 0; nt < 16; nt++) {
            float4 A = afp[nt*32];
            int hs = nt >> 3;
            ss[hs][0] = fmaf(D[nt].x, A.x, fmaf(D[nt].y, A.y, ss[hs][0]));
            ss[hs][1] = fmaf(D[nt].z, A.x, fmaf(D[nt].w, A.y, ss[hs][1]));
            sd[hs][0] = fmaf(D[nt].x, A.z, fmaf(D[nt].y, A.w, sd[hs][0]));
            sd[hs][1] = fmaf(D[nt].z, A.z, fmaf(D[nt].w, A.w, sd[hs][1]));
        }
        #pragma unroll
        for (int hs = 0; hs < 2; hs++)
            #pragma unroll
            for (int rs = 0; rs < 2; rs++) {
                #pragma unroll
                for (int o = 1; o < 4; o <<= 1) {
                    ss[hs][rs] += __shfl_xor_sync(0xffffffffu, ss[hs][rs], o);
                    sd[hs][rs] += __shfl_xor_sync(0xffffffffu, sd[hs][rs], o);
                }
            }
        if (q == 0) {
            #pragma unroll
            for (int hs = 0; hs < 2; hs++) {
                int h = 2*half + hs;
                alj[r*8 + h]     = ss[hs][0];
                alj[r*8 + 4 + h] = sd[hs][0];
                if (r + 8 < NN) {
                    alj[(r+8)*8 + h]     = ss[hs][1];
                    alj[(r+8)*8 + 4 + h] = sd[hs][1];
                }
            }
        }
    }
    __syncwarp();

    // ---- fused exp + normalized attention: M_w[half][hs][d][s] ----
    if (lane < 28) {
        int d = lane >> 1, hs = lane & 1, hh = 2*half + hs;
        float* Mrow = M_w + half*392 + hs*196 + d*14;
        float ad = alj[d*8 + 4 + hh];
        float dn = 0.f;
        int e1 = off[d+1];
        for (int e = off[d]; e < e1; e++) {
            int s = srcS[e];
            float v = alj[s*8 + hh] + ad;
            v = (v > 0.f) ? v : NEG * v;
            float ex = __expf(v);
            Mrow[s] += ex;
            dn += ex;
        }
        float inv = __fdividef(1.f, dn);
        #pragma unroll
        for (int s = 0; s < NN; s++) Mrow[s] *= inv;
    }

    // ---- stage h (= D) into smem [16][132] for column re-ownership ----
    {
        float* hb = h_sm + half*2112;
        #pragma unroll
        for (int nt = 0; nt < 16; nt++) {
            int c0 = nt*8 + 2*q;
            *(float2*)&hb[r*132 + c0]     = make_float2(D[nt].x, D[nt].y);
            *(float2*)&hb[(r+8)*132 + c0] = make_float2(D[nt].z, D[nt].w);
        }
    }
    __syncwarp();

    // ---- aggregation: thread owns 4 contiguous cols (lane*4), f32x2 packed ----
    {
        const float* hb = h_sm + half*2112;
        ulonglong2 hv[NN];
        #pragma unroll
        for (int s = 0; s < NN; s++)
            hv[s] = *(const ulonglong2*)&hb[s*132 + lane*4];

        const float* Mrow = M_w + half*392 + (lane >> 4)*196;
        ull* pb = part + half*448;
        #pragma unroll
        for (int n = 0; n < NN; n++) {
            ull a0 = 0ull, a1 = 0ull;
            #pragma unroll
            for (int s = 0; s < NN; s++) {
                float m = Mrow[n*14 + s];
                ull m2 = pk2(m, m);
                a0 = fma2(m2, hv[s].x, a0);
                a1 = fma2(m2, hv[s].y, a1);
            }
            a0 = add2(a0, __shfl_xor_sync(0xffffffffu, a0, 16));
            a1 = add2(a1, __shfl_xor_sync(0xffffffffu, a1, 16));
            if (lane < 16) {
                ulonglong2 v; v.x = a0; v.y = a1;
                *(ulonglong2*)&pb[n*32 + lane*2] = v;
            }
        }
    }
    __syncthreads();   // both warps' partials ready

    // ---- head mean + bias (+relu) (+cvt) -> x2_sm [16][68], pad rows zeroed ----
    {
        const float* p0 = (const float*)part;
        const float* p1 = (const float*)(part + 448);
        for (int i = t; i < 1024; i += 64) {
            int n = i >> 6, c = i & 63;
            float v = 0.f;
            if (n < NN) {
                v = 0.25f * (p0[n*64 + c] + p1[n*64 + c]) + bias[c];
                if (RELU) v = fmaxf(v, 0.f);
                if (CVT)  v = to_tf32(v);
            }
            x2_sm[n*68 + c] = v;
        }
    }
    __syncthreads();   // x2 ready
}

__global__ void __launch_bounds__(64, 5)
gat_kernel(const float* __restrict__ feature, const int* __restrict__ eraw,
           const float* __restrict__ b1v, const float* __restrict__ b2v,
           float* __restrict__ out, int E)
{
    __shared__ __align__(16) float x_sm[16*132];
    __shared__ __align__(16) float h_sm[2*16*132];
    __shared__ __align__(16) float x2_sm[16*68];
    __shared__ __align__(16) ull   part[2*448];
    __shared__ float M_w[2*392];
    __shared__ float alj[NN*8];
    __shared__ unsigned char srcS[MAXE];
    __shared__ int cnt[NN], off[NN+1];
    __shared__ float red[2];

    const int g = blockIdx.x;
    const int t = threadIdx.x;
    const int lane = t & 31, half = t >> 5;
    const int NE = E + NN;
    const int is64 = g_is64;

    // ---- load features (tf32-rounded) into x_sm [16][132]; zero pad rows ----
    {
        const float4* xg = (const float4*)(feature + (size_t)g * NN * FIN);
        for (int i = t; i < NN*32; i += 64) {
            int n = i >> 5, k4 = i & 31;
            float4 v = xg[i];
            v.x = to_tf32(v.x); v.y = to_tf32(v.y);
            v.z = to_tf32(v.z); v.w = to_tf32(v.w);
            *(float4*)&x_sm[n*132 + k4*4] = v;
        }
        for (int i = t; i < 2*132; i += 64) x_sm[14*132 + i] = 0.f;
    }

    // ---- warp 0: counting sort of edges by dst (self-loops appended) ----
    if (half == 0) {
        if (lane < NN) cnt[lane] = 0;
        __syncwarp();
        for (int e = lane; e < NE; e += 32) {
            int d;
            if (e < E) {
                size_t base = ((size_t)g * E + e) * 2;
                d = is64 ? (int)((const long long*)eraw)[base + 1] : eraw[base + 1];
            } else d = e - E;
            atomicAdd(&cnt[d], 1);
        }
        __syncwarp();
        if (lane == 0) {
            int s = 0;
            #pragma unroll
            for (int i = 0; i < NN; i++) { off[i] = s; s += cnt[i]; cnt[i] = off[i]; }
            off[NN] = s;
        }
        __syncwarp();
        for (int e = lane; e < NE; e += 32) {
            int s, d;
            if (e < E) {
                size_t base = ((size_t)g * E + e) * 2;
                if (is64) { const long long* p = (const long long*)eraw;
                            s = (int)p[base]; d = (int)p[base + 1]; }
                else      { s = eraw[base];   d = eraw[base + 1]; }
            } else { s = d = e - E; }
            int pos = atomicAdd(&cnt[d], 1);
            srcS[pos] = (unsigned char)s;
        }
    }
    __syncthreads();

    gat_layer<16, 132, true,  true >(g_W1f, g_af1, b1v, x_sm,  h_sm, x2_sm,
                                     M_w, alj, part, srcS, off, t, lane, half);
    gat_layer<8,  68,  false, false>(g_W2f, g_af2, b2v, x2_sm, h_sm, x2_sm,
                                     M_w, alj, part, srcS, off, t, lane, half);

    // ---- fused head: sigmoid(flat . w_fused + b_fused) ----
    float p = 0.f;
    for (int i = t; i < NN*NC; i += 64) {
        int n = i >> 6, c = i & 63;
        p = fmaf(x2_sm[n*68 + c], g_wfused[i], p);
    }
    #pragma unroll
    for (int o = 16; o; o >>= 1) p += __shfl_xor_sync(0xffffffffu, p, o);
    if (lane == 0) red[half] = p;
    __syncthreads();
    if (t == 0) {
        float s = g_bfused + red[0] + red[1];
        out[g] = 1.f / (1.f + __expf(-s));
    }
}

extern "C" void kernel_launch(void* const* d_in, const int* in_sizes, int n_in,
                              void* d_out, int out_size)
{
    const float* feature = (const float*)d_in[0];
    const int*   edges   = (const int*)  d_in[1];
    const float* W1   = (const float*)d_in[2];
    const float* as1  = (const float*)d_in[3];
    const float* ad1  = (const float*)d_in[4];
    const float* b1   = (const float*)d_in[5];
    const float* W2   = (const float*)d_in[6];
    const float* as2  = (const float*)d_in[7];
    const float* ad2  = (const float*)d_in[8];
    const float* b2   = (const float*)d_in[9];
    const float* Wlin = (const float*)d_in[10];
    const float* blin = (const float*)d_in[11];
    const float* Wpred= (const float*)d_in[12];
    const float* bpred= (const float*)d_in[13];

    int B = in_sizes[0] / (NN * FIN);       // 16384
    int E = in_sizes[1] / (2 * B);          // 182

    prep_kernel<<<48, 256>>>(W1, as1, ad1, W2, as2, ad2,
                             Wlin, blin, Wpred, bpred, edges);
    gat_kernel<<<B, 64>>>(feature, edges, b1, b2, (float*)d_out, E);
}

// round 11
// speedup vs baseline: 1.2062x; 1.2062x over previous
#include <cuda_runtime.h>

#define NN 14      // nodes per graph
#define NH 4       // heads
#define NC 64      // per-head channels
#define NO 256     // NH*NC
#define FIN 128
#define NEG 0.2f
#define MAXE 200   // >= E + NN = 196

typedef unsigned long long ull;
typedef unsigned int uint;

__device__ __forceinline__ ull pk2(float x, float y) {
    ull r; asm("mov.b64 %0, {%1, %2};" : "=l"(r) : "f"(x), "f"(y)); return r;
}
__device__ __forceinline__ ull fma2(ull a, ull b, ull c) {
    ull d; asm("fma.rn.f32x2 %0, %1, %2, %3;" : "=l"(d) : "l"(a), "l"(b), "l"(c)); return d;
}
__device__ __forceinline__ ull add2(ull a, ull b) {
    ull d; asm("add.rn.f32x2 %0, %1, %2;" : "=l"(d) : "l"(a), "l"(b)); return d;
}
__device__ __forceinline__ float to_tf32(float x) {
    uint u; asm("cvt.rna.tf32.f32 %0, %1;" : "=r"(u) : "f"(x));
    return __uint_as_float(u);
}
// D(16x8,f32) += A(16x8,tf32) @ B(8x8,tf32)
__device__ __forceinline__ void mma_tf32(float4& d, uint a0, uint a1, uint a2, uint a3,
                                         uint b0, uint b1) {
    asm("mma.sync.aligned.m16n8k8.row.col.f32.tf32.tf32.f32 "
        "{%0,%1,%2,%3}, {%4,%5,%6,%7}, {%8,%9}, {%0,%1,%2,%3};"
        : "+f"(d.x), "+f"(d.y), "+f"(d.z), "+f"(d.w)
        : "r"(a0), "r"(a1), "r"(a2), "r"(a3), "r"(b0), "r"(b1));
}

// ---- precomputed weights ----
// B-fragment-major: g_Wf[(kt*32 + j)*32 + lane] = {W[kt*8 + lane%4][j*8 + lane/4],
//                                                  W[kt*8 + lane%4 + 4][j*8 + lane/4]}  (tf32)
__device__ float2 g_W1f[16 * 32 * 32];
__device__ float2 g_W2f[8 * 32 * 32];
// a-vecs in D-fragment layout: j = half*16+nt, h = 2*half + (nt>>3),
// c = (nt&7)*8 + 2*(lane&3): {as[h][c], as[h][c+1], ad[h][c], ad[h][c+1]}
__device__ float4 g_af1[32 * 32];
__device__ float4 g_af2[32 * 32];
__device__ float  g_wfused[NN * NC];   // W_lin @ W_pred
__device__ float  g_bfused;
__device__ int    g_is64;

__global__ void prep_kernel(const float* __restrict__ W1, const float* __restrict__ as1,
                            const float* __restrict__ ad1,
                            const float* __restrict__ W2, const float* __restrict__ as2,
                            const float* __restrict__ ad2,
                            const float* __restrict__ Wlin, const float* __restrict__ blin,
                            const float* __restrict__ Wpred, const float* __restrict__ bpred,
                            const int* __restrict__ edges)
{
    int tid = blockIdx.x * blockDim.x + threadIdx.x;
    int nt  = gridDim.x * blockDim.x;

    for (int i = tid; i < 16*32*32; i += nt) {
        int kt = i >> 10, r = i & 1023, j = r >> 5, lane = r & 31;
        int k0 = kt*8 + (lane & 3), n = j*8 + (lane >> 2);
        g_W1f[i] = make_float2(to_tf32(W1[k0*NO + n]), to_tf32(W1[(k0+4)*NO + n]));
    }
    for (int i = tid; i < 8*32*32; i += nt) {
        int kt = i >> 10, r = i & 1023, j = r >> 5, lane = r & 31;
        int k0 = kt*8 + (lane & 3), n = j*8 + (lane >> 2);
        g_W2f[i] = make_float2(to_tf32(W2[k0*NO + n]), to_tf32(W2[(k0+4)*NO + n]));
    }
    for (int i = tid; i < 32*32; i += nt) {
        int j = i >> 5, lane = i & 31;
        int half = j >> 4, ntile = j & 15;
        int h = 2*half + (ntile >> 3);
        int c = (ntile & 7)*8 + 2*(lane & 3);
        g_af1[i] = make_float4(as1[h*NC + c], as1[h*NC + c + 1],
                               ad1[h*NC + c], ad1[h*NC + c + 1]);
        g_af2[i] = make_float4(as2[h*NC + c], as2[h*NC + c + 1],
                               ad2[h*NC + c], ad2[h*NC + c + 1]);
    }
    for (int i = tid; i < NN * NC; i += nt) {
        float s = 0.f;
        #pragma unroll
        for (int j = 0; j < NC/2; j++) s = fmaf(Wlin[i*(NC/2) + j], Wpred[j], s);
        g_wfused[i] = s;
    }
    if (tid == 0) {
        float s = bpred[0];
        #pragma unroll
        for (int j = 0; j < NC/2; j++) s = fmaf(blin[j], Wpred[j], s);
        g_bfused = s;
        int any = 0;
        #pragma unroll
        for (int k = 1; k < 256; k += 2) any |= edges[k];
        g_is64 = (any == 0) ? 1 : 0;
    }
}

// One GAT layer for one graph (2-warp CTA; this warp owns half = cols 128h..,
// heads 2h,2h+1). Input xa [16 rows, stride XST]; h staged into stg (stg0
// aliases layer-1's x buffer — barrier before staging makes that safe).
// Output -> x2_sm [16][68].
template<int KT, int XST, bool RELU, bool CVT>
__device__ __forceinline__ void gat_layer(
    const float2* __restrict__ Wf, const float4* __restrict__ af,
    const float* __restrict__ bias,
    const float* xa, float* stg0, float* stg1, float* x2_sm,
    float* M_w, float* alj, ull* part,
    const unsigned char* srcS, const int* off,
    int t, int lane, int half)
{
    const int r = lane >> 2, q = lane & 3;

    // zero this warp's M region (2 heads x 14 x 14)
    {
        float* Mz = M_w + half*392;
        for (int i = lane; i < 392; i += 32) Mz[i] = 0.f;
    }

    // ---- GEMM via tf32 mma: D[nt] = x(16xK) @ W(Kx8) for 16 n-tiles ----
    float4 D[16];
    #pragma unroll
    for (int nt = 0; nt < 16; nt++) D[nt] = make_float4(0.f, 0.f, 0.f, 0.f);

    const float2* wp = Wf + (half*16)*32 + lane;
    #pragma unroll 2
    for (int kt = 0; kt < KT; kt++) {
        uint a0 = __float_as_uint(xa[r*XST + kt*8 + q]);
        uint a1 = __float_as_uint(xa[(r+8)*XST + kt*8 + q]);
        uint a2 = __float_as_uint(xa[r*XST + kt*8 + q + 4]);
        uint a3 = __float_as_uint(xa[(r+8)*XST + kt*8 + q + 4]);
        #pragma unroll
        for (int nt = 0; nt < 16; nt++) {
            float2 b = wp[kt*1024 + nt*32];
            mma_tf32(D[nt], a0, a1, a2, a3,
                     __float_as_uint(b.x), __float_as_uint(b.y));
        }
    }

    // ---- attention logits from D fragments ----
    {
        float ss[2][2] = {{0.f,0.f},{0.f,0.f}};   // [head-sel][row-sel]
        float sd[2][2] = {{0.f,0.f},{0.f,0.f}};
        const float4* afp = af + (half*16)*32 + lane;
        #pragma unroll
        for (int nt = 0; nt < 16; nt++) {
            float4 A = afp[nt*32];
            int hs = nt >> 3;
            ss[hs][0] = fmaf(D[nt].x, A.x, fmaf(D[nt].y, A.y, ss[hs][0]));
            ss[hs][1] = fmaf(D[nt].z, A.x, fmaf(D[nt].w, A.y, ss[hs][1]));
            sd[hs][0] = fmaf(D[nt].x, A.z, fmaf(D[nt].y, A.w, sd[hs][0]));
            sd[hs][1] = fmaf(D[nt].z, A.z, fmaf(D[nt].w, A.w, sd[hs][1]));
        }
        #pragma unroll
        for (int hs = 0; hs < 2; hs++)
            #pragma unroll
            for (int rs = 0; rs < 2; rs++) {
                #pragma unroll
                for (int o = 1; o < 4; o <<= 1) {
                    ss[hs][rs] += __shfl_xor_sync(0xffffffffu, ss[hs][rs], o);
                    sd[hs][rs] += __shfl_xor_sync(0xffffffffu, sd[hs][rs], o);
                }
            }
        if (q == 0) {
            #pragma unroll
            for (int hs = 0; hs < 2; hs++) {
                int h = 2*half + hs;
                alj[r*8 + h]     = ss[hs][0];
                alj[r*8 + 4 + h] = sd[hs][0];
                if (r + 8 < NN) {
                    alj[(r+8)*8 + h]     = ss[hs][1];
                    alj[(r+8)*8 + 4 + h] = sd[hs][1];
                }
            }
        }
    }
    __syncwarp();

    // ---- fused exp + normalized attention: M_w[half][hs][d][s] ----
    if (lane < 28) {
        int d = lane >> 1, hs = lane & 1, hh = 2*half + hs;
        float* Mrow = M_w + half*392 + hs*196 + d*14;
        float ad = alj[d*8 + 4 + hh];
        float dn = 0.f;
        int e1 = off[d+1];
        for (int e = off[d]; e < e1; e++) {
            int s = srcS[e];
            float v = alj[s*8 + hh] + ad;
            v = (v > 0.f) ? v : NEG * v;
            float ex = __expf(v);
            Mrow[s] += ex;
            dn += ex;
        }
        float inv = __fdividef(1.f, dn);
        #pragma unroll
        for (int s = 0; s < NN; s++) Mrow[s] *= inv;
    }
    __syncthreads();   // all GEMM x-reads done: staging may overwrite x buffer

    // ---- stage h (= D) into smem [16][132] for column re-ownership ----
    {
        float* hb = half ? stg1 : stg0;
        #pragma unroll
        for (int nt = 0; nt < 16; nt++) {
            int c0 = nt*8 + 2*q;
            *(float2*)&hb[r*132 + c0]     = make_float2(D[nt].x, D[nt].y);
            *(float2*)&hb[(r+8)*132 + c0] = make_float2(D[nt].z, D[nt].w);
        }
    }
    __syncwarp();

    // ---- aggregation: thread owns 4 contiguous cols (lane*4), f32x2 packed ----
    {
        const float* hb = half ? stg1 : stg0;
        ulonglong2 hv[NN];
        #pragma unroll
        for (int s = 0; s < NN; s++)
            hv[s] = *(const ulonglong2*)&hb[s*132 + lane*4];

        const float* Mrow = M_w + half*392 + (lane >> 4)*196;
        ull* pb = part + half*448;
        #pragma unroll
        for (int n = 0; n < NN; n++) {
            ull a0 = 0ull, a1 = 0ull;
            #pragma unroll
            for (int s = 0; s < NN; s++) {
                float m = Mrow[n*14 + s];
                ull m2 = pk2(m, m);
                a0 = fma2(m2, hv[s].x, a0);
                a1 = fma2(m2, hv[s].y, a1);
            }
            a0 = add2(a0, __shfl_xor_sync(0xffffffffu, a0, 16));
            a1 = add2(a1, __shfl_xor_sync(0xffffffffu, a1, 16));
            if (lane < 16) {
                ulonglong2 v; v.x = a0; v.y = a1;
                *(ulonglong2*)&pb[n*32 + lane*2] = v;
            }
        }
    }
    __syncthreads();   // both warps' partials ready

    // ---- head mean + bias (+relu) (+cvt) -> x2_sm [16][68], pad rows zeroed ----
    {
        const float* p0 = (const float*)part;
        const float* p1 = (const float*)(part + 448);
        for (int i = t; i < 1024; i += 64) {
            int n = i >> 6, c = i & 63;
            float v = 0.f;
            if (n < NN) {
                v = 0.25f * (p0[n*64 + c] + p1[n*64 + c]) + bias[c];
                if (RELU) v = fmaxf(v, 0.f);
                if (CVT)  v = to_tf32(v);
            }
            x2_sm[n*68 + c] = v;
        }
    }
    __syncthreads();   // x2 ready
}

__global__ void __launch_bounds__(64, 7)
gat_kernel(const float* __restrict__ feature, const int* __restrict__ eraw,
           const float* __restrict__ b1v, const float* __restrict__ b2v,
           float* __restrict__ out, int E)
{
    __shared__ __align__(16) float x_sm[16*132];   // features; reused as h-stage half0
    __shared__ __align__(16) float h1_sm[16*132];  // h-stage half1
    __shared__ __align__(16) float x2_sm[16*68];
    __shared__ __align__(16) ull   part[2*448];
    __shared__ float M_w[2*392];
    __shared__ float alj[NN*8];
    __shared__ unsigned char srcS[MAXE];
    __shared__ int cnt[NN], off[NN+1];
    __shared__ float red[2];

    const int g = blockIdx.x;
    const int t = threadIdx.x;
    const int lane = t & 31, half = t >> 5;
    const int NE = E + NN;
    const int is64 = g_is64;

    if (half == 1) {
        // ---- warp 1: load features (tf32-rounded) into x_sm [16][132] ----
        const float4* xg = (const float4*)(feature + (size_t)g * NN * FIN);
        for (int i = lane; i < NN*32; i += 32) {
            int n = i >> 5, k4 = i & 31;
            float4 v = xg[i];
            v.x = to_tf32(v.x); v.y = to_tf32(v.y);
            v.z = to_tf32(v.z); v.w = to_tf32(v.w);
            *(float4*)&x_sm[n*132 + k4*4] = v;
        }
        for (int i = lane; i < 2*132; i += 32) x_sm[14*132 + i] = 0.f;
    } else {
        // ---- warp 0: counting sort of edges by dst (self-loops appended) ----
        if (lane < NN) cnt[lane] = 0;
        __syncwarp();
        for (int e = lane; e < NE; e += 32) {
            int d;
            if (e < E) {
                size_t base = ((size_t)g * E + e) * 2;
                d = is64 ? (int)((const long long*)eraw)[base + 1] : eraw[base + 1];
            } else d = e - E;
            atomicAdd(&cnt[d], 1);
        }
        __syncwarp();
        if (lane == 0) {
            int s = 0;
            #pragma unroll
            for (int i = 0; i < NN; i++) { off[i] = s; s += cnt[i]; cnt[i] = off[i]; }
            off[NN] = s;
        }
        __syncwarp();
        for (int e = lane; e < NE; e += 32) {
            int s, d;
            if (e < E) {
                size_t base = ((size_t)g * E + e) * 2;
                if (is64) { const long long* p = (const long long*)eraw;
                            s = (int)p[base]; d = (int)p[base + 1]; }
                else      { s = eraw[base];   d = eraw[base + 1]; }
            } else { s = d = e - E; }
            int pos = atomicAdd(&cnt[d], 1);
            srcS[pos] = (unsigned char)s;
        }
    }
    __syncthreads();

    gat_layer<16, 132, true,  true >(g_W1f, g_af1, b1v, x_sm,  x_sm, h1_sm, x2_sm,
                                     M_w, alj, part, srcS, off, t, lane, half);
    gat_layer<8,  68,  false, false>(g_W2f, g_af2, b2v, x2_sm, x_sm, h1_sm, x2_sm,
                                     M_w, alj, part, srcS, off, t, lane, half);

    // ---- fused head: sigmoid(flat . w_fused + b_fused) ----
    float p = 0.f;
    for (int i = t; i < NN*NC; i += 64) {
        int n = i >> 6, c = i & 63;
        p = fmaf(x2_sm[n*68 + c], g_wfused[i], p);
    }
    #pragma unroll
    for (int o = 16; o; o >>= 1) p += __shfl_xor_sync(0xffffffffu, p, o);
    if (lane == 0) red[half] = p;
    __syncthreads();
    if (t == 0) {
        float s = g_bfused + red[0] + red[1];
        out[g] = 1.f / (1.f + __expf(-s));
    }
}

extern "C" void kernel_launch(void* const* d_in, const int* in_sizes, int n_in,
                              void* d_out, int out_size)
{
    const float* feature = (const float*)d_in[0];
    const int*   edges   = (const int*)  d_in[1];
    const float* W1   = (const float*)d_in[2];
    const float* as1  = (const float*)d_in[3];
    const float* ad1  = (const float*)d_in[4];
    const float* b1   = (const float*)d_in[5];
    const float* W2   = (const float*)d_in[6];
    const float* as2  = (const float*)d_in[7];
    const float* ad2  = (const float*)d_in[8];
    const float* b2   = (const float*)d_in[9];
    const float* Wlin = (const float*)d_in[10];
    const float* blin = (const float*)d_in[11];
    const float* Wpred= (const float*)d_in[12];
    const float* bpred= (const float*)d_in[13];

    int B = in_sizes[0] / (NN * FIN);       // 16384
    int E = in_sizes[1] / (2 * B);          // 182

    prep_kernel<<<48, 256>>>(W1, as1, ad1, W2, as2, ad2,
                             Wlin, blin, Wpred, bpred, edges);
    gat_kernel<<<B, 64>>>(feature, edges, b1, b2, (float*)d_out, E);
}

// round 12
// speedup vs baseline: 1.4200x; 1.1773x over previous
#include <cuda_runtime.h>

#define NN 14      // nodes per graph
#define NH 4       // heads
#define NC 64      // per-head channels
#define NO 256     // NH*NC
#define FIN 128
#define NEG 0.2f
#define MAXE 200   // >= E + NN = 196

typedef unsigned long long ull;
typedef unsigned int uint;

__device__ __forceinline__ ull pk2(float x, float y) {
    ull r; asm("mov.b64 %0, {%1, %2};" : "=l"(r) : "f"(x), "f"(y)); return r;
}
__device__ __forceinline__ ull fma2(ull a, ull b, ull c) {
    ull d; asm("fma.rn.f32x2 %0, %1, %2, %3;" : "=l"(d) : "l"(a), "l"(b), "l"(c)); return d;
}
__device__ __forceinline__ ull add2(ull a, ull b) {
    ull d; asm("add.rn.f32x2 %0, %1, %2;" : "=l"(d) : "l"(a), "l"(b)); return d;
}
__device__ __forceinline__ float to_tf32(float x) {
    uint u; asm("cvt.rna.tf32.f32 %0, %1;" : "=r"(u) : "f"(x));
    return __uint_as_float(u);
}
// D(16x8,f32) += A(16x8,tf32) @ B(8x8,tf32)
__device__ __forceinline__ void mma_tf32(float4& d, uint a0, uint a1, uint a2, uint a3,
                                         uint b0, uint b1) {
    asm("mma.sync.aligned.m16n8k8.row.col.f32.tf32.tf32.f32 "
        "{%0,%1,%2,%3}, {%4,%5,%6,%7}, {%8,%9}, {%0,%1,%2,%3};"
        : "+f"(d.x), "+f"(d.y), "+f"(d.z), "+f"(d.w)
        : "r"(a0), "r"(a1), "r"(a2), "r"(a3), "r"(b0), "r"(b1));
}

// ---- precomputed weights ----
// B-fragment-major: g_Wf[(kt*32 + j)*32 + lane] = {W[kt*8 + lane%4][j*8 + lane/4],
//                                                  W[kt*8 + lane%4 + 4][j*8 + lane/4]}  (tf32)
__device__ float2 g_W1f[16 * 32 * 32];
__device__ float2 g_W2f[8 * 32 * 32];
// a-vecs in D-fragment layout
__device__ float4 g_af1[32 * 32];
__device__ float4 g_af2[32 * 32];
__device__ float  g_wfused[NN * NC];   // W_lin @ W_pred
__device__ float  g_bfused;
__device__ int    g_is64;

__global__ void prep_kernel(const float* __restrict__ W1, const float* __restrict__ as1,
                            const float* __restrict__ ad1,
                            const float* __restrict__ W2, const float* __restrict__ as2,
                            const float* __restrict__ ad2,
                            const float* __restrict__ Wlin, const float* __restrict__ blin,
                            const float* __restrict__ Wpred, const float* __restrict__ bpred,
                            const int* __restrict__ edges)
{
    int tid = blockIdx.x * blockDim.x + threadIdx.x;
    int nt  = gridDim.x * blockDim.x;

    for (int i = tid; i < 16*32*32; i += nt) {
        int kt = i >> 10, r = i & 1023, j = r >> 5, lane = r & 31;
        int k0 = kt*8 + (lane & 3), n = j*8 + (lane >> 2);
        g_W1f[i] = make_float2(to_tf32(W1[k0*NO + n]), to_tf32(W1[(k0+4)*NO + n]));
    }
    for (int i = tid; i < 8*32*32; i += nt) {
        int kt = i >> 10, r = i & 1023, j = r >> 5, lane = r & 31;
        int k0 = kt*8 + (lane & 3), n = j*8 + (lane >> 2);
        g_W2f[i] = make_float2(to_tf32(W2[k0*NO + n]), to_tf32(W2[(k0+4)*NO + n]));
    }
    for (int i = tid; i < 32*32; i += nt) {
        int j = i >> 5, lane = i & 31;
        int half = j >> 4, ntile = j & 15;
        int h = 2*half + (ntile >> 3);
        int c = (ntile & 7)*8 + 2*(lane & 3);
        g_af1[i] = make_float4(as1[h*NC + c], as1[h*NC + c + 1],
                               ad1[h*NC + c], ad1[h*NC + c + 1]);
        g_af2[i] = make_float4(as2[h*NC + c], as2[h*NC + c + 1],
                               ad2[h*NC + c], ad2[h*NC + c + 1]);
    }
    for (int i = tid; i < NN * NC; i += nt) {
        float s = 0.f;
        #pragma unroll
        for (int j = 0; j < NC/2; j++) s = fmaf(Wlin[i*(NC/2) + j], Wpred[j], s);
        g_wfused[i] = s;
    }
    if (tid == 0) {
        float s = bpred[0];
        #pragma unroll
        for (int j = 0; j < NC/2; j++) s = fmaf(blin[j], Wpred[j], s);
        g_bfused = s;
        int any = 0;
        #pragma unroll
        for (int k = 1; k < 256; k += 2) any |= edges[k];
        g_is64 = (any == 0) ? 1 : 0;
    }
}

// One GAT layer for one graph (2-warp CTA; this warp owns half = cols 128h..,
// heads 2h,2h+1). Input xa [16 rows, stride XST].
// Staging buffers stg0/stg1 (one per warp) are reused as: h-stage, then
// aggregation-partial store (bytes 0..3584). Output -> xout [16][68].
template<int KT, int XST, bool RELU, bool CVT>
__device__ __forceinline__ void gat_layer(
    const float2* __restrict__ Wf, const float4* __restrict__ af,
    const float* __restrict__ bias,
    const float* xa, float* stg0, float* stg1, float* xout,
    float* M_w, float* alj,
    const unsigned char* srcS, const int* off,
    int t, int lane, int half)
{
    const int r = lane >> 2, q = lane & 3;

    // zero this warp's M region (2 heads x 14 x 14)
    {
        float* Mz = M_w + half*392;
        for (int i = lane; i < 392; i += 32) Mz[i] = 0.f;
    }

    // ---- GEMM via tf32 mma: D[nt] = x(16xK) @ W(Kx8) for 16 n-tiles ----
    float4 D[16];
    #pragma unroll
    for (int nt = 0; nt < 16; nt++) D[nt] = make_float4(0.f, 0.f, 0.f, 0.f);

    const float2* wp = Wf + (half*16)*32 + lane;
    #pragma unroll 2
    for (int kt = 0; kt < KT; kt++) {
        uint a0 = __float_as_uint(xa[r*XST + kt*8 + q]);
        uint a1 = __float_as_uint(xa[(r+8)*XST + kt*8 + q]);
        uint a2 = __float_as_uint(xa[r*XST + kt*8 + q + 4]);
        uint a3 = __float_as_uint(xa[(r+8)*XST + kt*8 + q + 4]);
        #pragma unroll
        for (int nt = 0; nt < 16; nt++) {
            float2 b = wp[kt*1024 + nt*32];
            mma_tf32(D[nt], a0, a1, a2, a3,
                     __float_as_uint(b.x), __float_as_uint(b.y));
        }
    }

    // ---- attention logits from D fragments ----
    {
        float ss[2][2] = {{0.f,0.f},{0.f,0.f}};   // [head-sel][row-sel]
        float sd[2][2] = {{0.f,0.f},{0.f,0.f}};
        const float4* afp = af + (half*16)*32 + lane;
        #pragma unroll
        for (int nt = 0; nt < 16; nt++) {
            float4 A = afp[nt*32];
            int hs = nt >> 3;
            ss[hs][0] = fmaf(D[nt].x, A.x, fmaf(D[nt].y, A.y, ss[hs][0]));
            ss[hs][1] = fmaf(D[nt].z, A.x, fmaf(D[nt].w, A.y, ss[hs][1]));
            sd[hs][0] = fmaf(D[nt].x, A.z, fmaf(D[nt].y, A.w, sd[hs][0]));
            sd[hs][1] = fmaf(D[nt].z, A.z, fmaf(D[nt].w, A.w, sd[hs][1]));
        }
        #pragma unroll
        for (int hs = 0; hs < 2; hs++)
            #pragma unroll
            for (int rs = 0; rs < 2; rs++) {
                #pragma unroll
                for (int o = 1; o < 4; o <<= 1) {
                    ss[hs][rs] += __shfl_xor_sync(0xffffffffu, ss[hs][rs], o);
                    sd[hs][rs] += __shfl_xor_sync(0xffffffffu, sd[hs][rs], o);
                }
            }
        if (q == 0) {
            #pragma unroll
            for (int hs = 0; hs < 2; hs++) {
                int h = 2*half + hs;
                alj[r*8 + h]     = ss[hs][0];
                alj[r*8 + 4 + h] = sd[hs][0];
                if (r + 8 < NN) {
                    alj[(r+8)*8 + h]     = ss[hs][1];
                    alj[(r+8)*8 + 4 + h] = sd[hs][1];
                }
            }
        }
    }
    __syncwarp();

    // ---- fused exp + normalized attention: M_w[half][hs][d][s] ----
    if (lane < 28) {
        int d = lane >> 1, hs = lane & 1, hh = 2*half + hs;
        float* Mrow = M_w + half*392 + hs*196 + d*14;
        float ad = alj[d*8 + 4 + hh];
        float dn = 0.f;
        int e1 = off[d+1];
        for (int e = off[d]; e < e1; e++) {
            int s = srcS[e];
            float v = alj[s*8 + hh] + ad;
            v = (v > 0.f) ? v : NEG * v;
            float ex = __expf(v);
            Mrow[s] += ex;
            dn += ex;
        }
        float inv = __fdividef(1.f, dn);
        #pragma unroll
        for (int s = 0; s < NN; s++) Mrow[s] *= inv;
    }
    __syncthreads();   // all GEMM x-reads done: staging may overwrite x buffer

    // ---- stage h (= D) into this warp's buffer [16][132] ----
    float* hb = half ? stg1 : stg0;
    {
        #pragma unroll
        for (int nt = 0; nt < 16; nt++) {
            int c0 = nt*8 + 2*q;
            *(float2*)&hb[r*132 + c0]     = make_float2(D[nt].x, D[nt].y);
            *(float2*)&hb[(r+8)*132 + c0] = make_float2(D[nt].z, D[nt].w);
        }
    }
    __syncwarp();

    // ---- aggregation: thread owns 4 contiguous cols (lane*4), f32x2 packed.
    //      Partials are written back into the LOW bytes of hb (hv is fully
    //      register-resident before any store; __syncwarp separates). ----
    {
        ulonglong2 hv[NN];
        #pragma unroll
        for (int s = 0; s < NN; s++)
            hv[s] = *(const ulonglong2*)&hb[s*132 + lane*4];
        __syncwarp();   // all lanes' hv loads complete before stores below

        const float* Mrow = M_w + half*392 + (lane >> 4)*196;
        ull* pb = (ull*)hb;
        #pragma unroll
        for (int n = 0; n < NN; n++) {
            ull a0 = 0ull, a1 = 0ull;
            #pragma unroll
            for (int s = 0; s < NN; s++) {
                float m = Mrow[n*14 + s];
                ull m2 = pk2(m, m);
                a0 = fma2(m2, hv[s].x, a0);
                a1 = fma2(m2, hv[s].y, a1);
            }
            a0 = add2(a0, __shfl_xor_sync(0xffffffffu, a0, 16));
            a1 = add2(a1, __shfl_xor_sync(0xffffffffu, a1, 16));
            if (lane < 16) {
                ulonglong2 v; v.x = a0; v.y = a1;
                *(ulonglong2*)&pb[n*32 + lane*2] = v;
            }
        }
    }
    __syncthreads();   // both warps' partials ready

    // ---- head mean + bias (+relu) (+cvt) -> xout [16][68] (disjoint from
    //      the 3584-byte partial regions at the base of stg0/stg1) ----
    {
        const float* p0 = stg0;
        const float* p1 = stg1;
        for (int i = t; i < 1024; i += 64) {
            int n = i >> 6, c = i & 63;
            float v = 0.f;
            if (n < NN) {
                v = 0.25f * (p0[n*64 + c] + p1[n*64 + c]) + bias[c];
                if (RELU) v = fmaxf(v, 0.f);
                if (CVT)  v = to_tf32(v);
            }
            xout[n*68 + c] = v;
        }
    }
    __syncthreads();   // xout ready
}

__global__ void __launch_bounds__(64, 8)
gat_kernel(const float* __restrict__ feature, const int* __restrict__ eraw,
           const float* __restrict__ b1v, const float* __restrict__ b2v,
           float* __restrict__ out, int E)
{
    // x_sm: features / warp0 h-stage+partials / x2 output at float offset 1024
    __shared__ __align__(16) float x_sm[16*132];
    __shared__ __align__(16) float h1_sm[16*132];  // warp1 h-stage+partials
    __shared__ float M_w[2*392];
    __shared__ float alj[NN*8];
    __shared__ unsigned char srcS[MAXE];
    __shared__ int cnt[NN], off[NN+1];
    __shared__ float red[2];

    const int g = blockIdx.x;
    const int t = threadIdx.x;
    const int lane = t & 31, half = t >> 5;
    const int NE = E + NN;
    const int is64 = g_is64;
    float* x2 = x_sm + 1024;   // [16][68], bytes 4096..8448 of x_sm

    if (half == 1) {
        // ---- warp 1: load features (tf32-rounded) into x_sm [16][132] ----
        const float4* xg = (const float4*)(feature + (size_t)g * NN * FIN);
        for (int i = lane; i < NN*32; i += 32) {
            int n = i >> 5, k4 = i & 31;
            float4 v = xg[i];
            v.x = to_tf32(v.x); v.y = to_tf32(v.y);
            v.z = to_tf32(v.z); v.w = to_tf32(v.w);
            *(float4*)&x_sm[n*132 + k4*4] = v;
        }
        for (int i = lane; i < 2*132; i += 32) x_sm[14*132 + i] = 0.f;
    } else {
        // ---- warp 0: counting sort of edges by dst (self-loops appended) ----
        if (lane < NN) cnt[lane] = 0;
        __syncwarp();
        for (int e = lane; e < NE; e += 32) {
            int d;
            if (e < E) {
                size_t base = ((size_t)g * E + e) * 2;
                d = is64 ? (int)((const long long*)eraw)[base + 1] : eraw[base + 1];
            } else d = e - E;
            atomicAdd(&cnt[d], 1);
        }
        __syncwarp();
        if (lane == 0) {
            int s = 0;
            #pragma unroll
            for (int i = 0; i < NN; i++) { off[i] = s; s += cnt[i]; cnt[i] = off[i]; }
            off[NN] = s;
        }
        __syncwarp();
        for (int e = lane; e < NE; e += 32) {
            int s, d;
            if (e < E) {
                size_t base = ((size_t)g * E + e) * 2;
                if (is64) { const long long* p = (const long long*)eraw;
                            s = (int)p[base]; d = (int)p[base + 1]; }
                else      { s = eraw[base];   d = eraw[base + 1]; }
            } else { s = d = e - E; }
            int pos = atomicAdd(&cnt[d], 1);
            srcS[pos] = (unsigned char)s;
        }
    }
    __syncthreads();

    gat_layer<16, 132, true,  true >(g_W1f, g_af1, b1v, x_sm, x_sm, h1_sm, x2,
                                     M_w, alj, srcS, off, t, lane, half);
    gat_layer<8,  68,  false, false>(g_W2f, g_af2, b2v, x2,   x_sm, h1_sm, x2,
                                     M_w, alj, srcS, off, t, lane, half);

    // ---- fused head: sigmoid(flat . w_fused + b_fused) ----
    float p = 0.f;
    for (int i = t; i < NN*NC; i += 64) {
        int n = i >> 6, c = i & 63;
        p = fmaf(x2[n*68 + c], g_wfused[i], p);
    }
    #pragma unroll
    for (int o = 16; o; o >>= 1) p += __shfl_xor_sync(0xffffffffu, p, o);
    if (lane == 0) red[half] = p;
    __syncthreads();
    if (t == 0) {
        float s = g_bfused + red[0] + red[1];
        out[g] = 1.f / (1.f + __expf(-s));
    }
}

extern "C" void kernel_launch(void* const* d_in, const int* in_sizes, int n_in,
                              void* d_out, int out_size)
{
    const float* feature = (const float*)d_in[0];
    const int*   edges   = (const int*)  d_in[1];
    const float* W1   = (const float*)d_in[2];
    const float* as1  = (const float*)d_in[3];
    const float* ad1  = (const float*)d_in[4];
    const float* b1   = (const float*)d_in[5];
    const float* W2   = (const float*)d_in[6];
    const float* as2  = (const float*)d_in[7];
    const float* ad2  = (const float*)d_in[8];
    const float* b2   = (const float*)d_in[9];
    const float* Wlin = (const float*)d_in[10];
    const float* blin = (const float*)d_in[11];
    const float* Wpred= (const float*)d_in[12];
    const float* bpred= (const float*)d_in[13];

    int B = in_sizes[0] / (NN * FIN);       // 16384
    int E = in_sizes[1] / (2 * B);          // 182

    prep_kernel<<<48, 256>>>(W1, as1, ad1, W2, as2, ad2,
                             Wlin, blin, Wpred, bpred, edges);
    gat_kernel<<<B, 64>>>(feature, edges, b1, b2, (float*)d_out, E);
}

// round 13
// speedup vs baseline: 1.6294x; 1.1475x over previous
#include <cuda_runtime.h>
#include <cuda_fp16.h>

#define NN 14      // nodes per graph
#define NH 4       // heads
#define NC 64      // per-head channels
#define NO 256     // NH*NC
#define FIN 128
#define NEG 0.2f
#define MAXE 200   // >= E + NN = 196

typedef unsigned long long ull;
typedef unsigned int uint;

__device__ __forceinline__ ull pk2(float x, float y) {
    ull r; asm("mov.b64 %0, {%1, %2};" : "=l"(r) : "f"(x), "f"(y)); return r;
}
__device__ __forceinline__ ull fma2(ull a, ull b, ull c) {
    ull d; asm("fma.rn.f32x2 %0, %1, %2, %3;" : "=l"(d) : "l"(a), "l"(b), "l"(c)); return d;
}
__device__ __forceinline__ ull add2(ull a, ull b) {
    ull d; asm("add.rn.f32x2 %0, %1, %2;" : "=l"(d) : "l"(a), "l"(b)); return d;
}
// D(16x8,f32) += A(16x16,f16) @ B(16x8,f16)
__device__ __forceinline__ void mma_f16(float4& d, uint a0, uint a1, uint a2, uint a3,
                                        uint b0, uint b1) {
    asm("mma.sync.aligned.m16n8k16.row.col.f32.f16.f16.f32 "
        "{%0,%1,%2,%3}, {%4,%5,%6,%7}, {%8,%9}, {%0,%1,%2,%3};"
        : "+f"(d.x), "+f"(d.y), "+f"(d.z), "+f"(d.w)
        : "r"(a0), "r"(a1), "r"(a2), "r"(a3), "r"(b0), "r"(b1));
}

// ---- precomputed weights ----
// B-fragment-major fp16: g_Wh[(kt*32 + nt)*32 + lane] = uint2{
//   half2{W[kt*16 + 2q][n], W[kt*16 + 2q+1][n]},
//   half2{W[kt*16 + 8 + 2q][n], W[kt*16 + 9 + 2q][n]} }  q=lane&3, n=nt*8+lane/4
__device__ uint2 g_W1h[8 * 32 * 32];
__device__ uint2 g_W2h[4 * 32 * 32];
// a-vecs in D-fragment layout: j = half*16+nt, h = 2*half + (nt>>3),
// c = (nt&7)*8 + 2*(lane&3): {as[h][c], as[h][c+1], ad[h][c], ad[h][c+1]}
__device__ float4 g_af1[32 * 32];
__device__ float4 g_af2[32 * 32];
__device__ float  g_wfused[NN * NC];   // W_lin @ W_pred
__device__ float  g_bfused;
__device__ int    g_is64;

__global__ void prep_kernel(const float* __restrict__ W1, const float* __restrict__ as1,
                            const float* __restrict__ ad1,
                            const float* __restrict__ W2, const float* __restrict__ as2,
                            const float* __restrict__ ad2,
                            const float* __restrict__ Wlin, const float* __restrict__ blin,
                            const float* __restrict__ Wpred, const float* __restrict__ bpred,
                            const int* __restrict__ edges)
{
    int tid = blockIdx.x * blockDim.x + threadIdx.x;
    int nt  = gridDim.x * blockDim.x;

    for (int i = tid; i < 8*32*32; i += nt) {
        int kt = i >> 10, r = i & 1023, ntile = r >> 5, lane = r & 31;
        int q = lane & 3, n = ntile*8 + (lane >> 2);
        int k0 = kt*16 + 2*q;
        __half2 b0 = __halves2half2(__float2half_rn(W1[k0*NO + n]),
                                    __float2half_rn(W1[(k0+1)*NO + n]));
        __half2 b1 = __halves2half2(__float2half_rn(W1[(k0+8)*NO + n]),
                                    __float2half_rn(W1[(k0+9)*NO + n]));
        g_W1h[i] = make_uint2(*(uint*)&b0, *(uint*)&b1);
    }
    for (int i = tid; i < 4*32*32; i += nt) {
        int kt = i >> 10, r = i & 1023, ntile = r >> 5, lane = r & 31;
        int q = lane & 3, n = ntile*8 + (lane >> 2);
        int k0 = kt*16 + 2*q;
        __half2 b0 = __halves2half2(__float2half_rn(W2[k0*NO + n]),
                                    __float2half_rn(W2[(k0+1)*NO + n]));
        __half2 b1 = __halves2half2(__float2half_rn(W2[(k0+8)*NO + n]),
                                    __float2half_rn(W2[(k0+9)*NO + n]));
        g_W2h[i] = make_uint2(*(uint*)&b0, *(uint*)&b1);
    }
    for (int i = tid; i < 32*32; i += nt) {
        int j = i >> 5, lane = i & 31;
        int half_ = j >> 4, ntile = j & 15;
        int h = 2*half_ + (ntile >> 3);
        int c = (ntile & 7)*8 + 2*(lane & 3);
        g_af1[i] = make_float4(as1[h*NC + c], as1[h*NC + c + 1],
                               ad1[h*NC + c], ad1[h*NC + c + 1]);
        g_af2[i] = make_float4(as2[h*NC + c], as2[h*NC + c + 1],
                               ad2[h*NC + c], ad2[h*NC + c + 1]);
    }
    for (int i = tid; i < NN * NC; i += nt) {
        float s = 0.f;
        #pragma unroll
        for (int j = 0; j < NC/2; j++) s = fmaf(Wlin[i*(NC/2) + j], Wpred[j], s);
        g_wfused[i] = s;
    }
    if (tid == 0) {
        float s = bpred[0];
        #pragma unroll
        for (int j = 0; j < NC/2; j++) s = fmaf(blin[j], Wpred[j], s);
        g_bfused = s;
        int any = 0;
        #pragma unroll
        for (int k = 1; k < 256; k += 2) any |= edges[k];
        g_is64 = (any == 0) ? 1 : 0;
    }
}

// One GAT layer for one graph (2-warp CTA; this warp owns half = cols 128h..,
// heads 2h,2h+1). Input xa: fp16 [16 rows, stride 136 halves].
// stg0/stg1: f32 staging [16][132] per warp, reused for agg partials.
// Output (head mean + bias (+relu), fp16) -> xout [16 rows, stride 136 halves].
template<int KT, bool RELU>
__device__ __forceinline__ void gat_layer(
    const uint2* __restrict__ Wh, const float4* __restrict__ af,
    const float* __restrict__ bias,
    const __half* xa, float* stg0, float* stg1, __half* xout,
    float* M_w, float* alj,
    const unsigned char* srcS, const int* off,
    int t, int lane, int half_)
{
    const int r = lane >> 2, q = lane & 3;

    // zero this warp's M region (2 heads x 14 x 14)
    {
        float* Mz = M_w + half_*392;
        for (int i = lane; i < 392; i += 32) Mz[i] = 0.f;
    }

    // ---- GEMM via fp16 mma: D[nt] = x(16xK) @ W(Kx8) for 16 n-tiles ----
    float4 D[16];
    #pragma unroll
    for (int nt = 0; nt < 16; nt++) D[nt] = make_float4(0.f, 0.f, 0.f, 0.f);

    const uint2* wp = Wh + (half_*16)*32 + lane;
    #pragma unroll 2
    for (int kt = 0; kt < KT; kt++) {
        int k0 = kt*16 + 2*q;
        uint a0 = *(const uint*)&xa[r*136 + k0];
        uint a1 = *(const uint*)&xa[(r+8)*136 + k0];
        uint a2 = *(const uint*)&xa[r*136 + k0 + 8];
        uint a3 = *(const uint*)&xa[(r+8)*136 + k0 + 8];
        #pragma unroll
        for (int nt = 0; nt < 16; nt++) {
            uint2 b = wp[kt*1024 + nt*32];
            mma_f16(D[nt], a0, a1, a2, a3, b.x, b.y);
        }
    }

    // ---- attention logits from D fragments ----
    {
        float ss[2][2] = {{0.f,0.f},{0.f,0.f}};   // [head-sel][row-sel]
        float sd[2][2] = {{0.f,0.f},{0.f,0.f}};
        const float4* afp = af + (half_*16)*32 + lane;
        #pragma unroll
        for (int nt = 0; nt < 16; nt++) {
            float4 A = afp[nt*32];
            int hs = nt >> 3;
            ss[hs][0] = fmaf(D[nt].x, A.x, fmaf(D[nt].y, A.y, ss[hs][0]));
            ss[hs][1] = fmaf(D[nt].z, A.x, fmaf(D[nt].w, A.y, ss[hs][1]));
            sd[hs][0] = fmaf(D[nt].x, A.z, fmaf(D[nt].y, A.w, sd[hs][0]));
            sd[hs][1] = fmaf(D[nt].z, A.z, fmaf(D[nt].w, A.w, sd[hs][1]));
        }
        #pragma unroll
        for (int hs = 0; hs < 2; hs++)
            #pragma unroll
            for (int rs = 0; rs < 2; rs++) {
                #pragma unroll
                for (int o = 1; o < 4; o <<= 1) {
                    ss[hs][rs] += __shfl_xor_sync(0xffffffffu, ss[hs][rs], o);
                    sd[hs][rs] += __shfl_xor_sync(0xffffffffu, sd[hs][rs], o);
                }
            }
        if (q == 0) {
            #pragma unroll
            for (int hs = 0; hs < 2; hs++) {
                int h = 2*half_ + hs;
                alj[r*8 + h]     = ss[hs][0];
                alj[r*8 + 4 + h] = sd[hs][0];
                if (r + 8 < NN) {
                    alj[(r+8)*8 + h]     = ss[hs][1];
                    alj[(r+8)*8 + 4 + h] = sd[hs][1];
                }
            }
        }
    }
    __syncwarp();

    // ---- fused exp + normalized attention: M_w[half][hs][d][s] ----
    if (lane < 28) {
        int d = lane >> 1, hs = lane & 1, hh = 2*half_ + hs;
        float* Mrow = M_w + half_*392 + hs*196 + d*14;
        float ad = alj[d*8 + 4 + hh];
        float dn = 0.f;
        int e1 = off[d+1];
        for (int e = off[d]; e < e1; e++) {
            int s = srcS[e];
            float v = alj[s*8 + hh] + ad;
            v = (v > 0.f) ? v : NEG * v;
            float ex = __expf(v);
            Mrow[s] += ex;
            dn += ex;
        }
        float inv = __fdividef(1.f, dn);
        #pragma unroll
        for (int s = 0; s < NN; s++) Mrow[s] *= inv;
    }
    __syncthreads();   // all GEMM x-reads done: staging may overwrite x buffer

    // ---- stage h (= D, f32) into this warp's buffer [16][132] ----
    float* hb = half_ ? stg1 : stg0;
    {
        #pragma unroll
        for (int nt = 0; nt < 16; nt++) {
            int c0 = nt*8 + 2*q;
            *(float2*)&hb[r*132 + c0]     = make_float2(D[nt].x, D[nt].y);
            *(float2*)&hb[(r+8)*132 + c0] = make_float2(D[nt].z, D[nt].w);
        }
    }
    __syncwarp();

    // ---- aggregation: thread owns 4 contiguous cols (lane*4), f32x2 packed.
    //      Partials go back into the LOW bytes of hb (hv register-resident). ----
    {
        ulonglong2 hv[NN];
        #pragma unroll
        for (int s = 0; s < NN; s++)
            hv[s] = *(const ulonglong2*)&hb[s*132 + lane*4];
        __syncwarp();   // all lanes' hv loads complete before stores below

        const float* Mrow = M_w + half_*392 + (lane >> 4)*196;
        ull* pb = (ull*)hb;
        #pragma unroll
        for (int n = 0; n < NN; n++) {
            ull a0 = 0ull, a1 = 0ull;
            #pragma unroll
            for (int s = 0; s < NN; s++) {
                float m = Mrow[n*14 + s];
                ull m2 = pk2(m, m);
                a0 = fma2(m2, hv[s].x, a0);
                a1 = fma2(m2, hv[s].y, a1);
            }
            a0 = add2(a0, __shfl_xor_sync(0xffffffffu, a0, 16));
            a1 = add2(a1, __shfl_xor_sync(0xffffffffu, a1, 16));
            if (lane < 16) {
                ulonglong2 v; v.x = a0; v.y = a1;
                *(ulonglong2*)&pb[n*32 + lane*2] = v;
            }
        }
    }
    __syncthreads();   // both warps' partials ready

    // ---- head mean + bias (+relu) -> xout fp16 [16][136]
    //      (xout sits at byte 4096 of stg0: disjoint from partials 0..3584) ----
    {
        const float* p0 = stg0;
        const float* p1 = stg1;
        for (int i = t; i < 1024; i += 64) {
            int n = i >> 6, c = i & 63;
            float v = 0.f;
            if (n < NN) {
                v = 0.25f * (p0[n*64 + c] + p1[n*64 + c]) + bias[c];
                if (RELU) v = fmaxf(v, 0.f);
            }
            xout[n*136 + c] = __float2half_rn(v);
        }
    }
    __syncthreads();   // xout ready
}

__global__ void __launch_bounds__(64, 8)
gat_kernel(const float* __restrict__ feature, const int* __restrict__ eraw,
           const float* __restrict__ b1v, const float* __restrict__ b2v,
           float* __restrict__ out, int E)
{
    // bufA: features (fp16, 4352B) / warp0 h-stage+partials (f32, 8448B) /
    //       layer output x2h (fp16) at byte offset 4096
    __shared__ __align__(16) float bufA[16*132];
    __shared__ __align__(16) float h1_sm[16*132];  // warp1 h-stage+partials
    __shared__ float M_w[2*392];
    __shared__ float alj[NN*8];
    __shared__ unsigned char srcS[MAXE];
    __shared__ int cnt[NN], off[NN+1];
    __shared__ float red[2];

    const int g = blockIdx.x;
    const int t = threadIdx.x;
    const int lane = t & 31, half_ = t >> 5;
    const int NE = E + NN;
    const int is64 = g_is64;
    __half* xh  = (__half*)bufA;            // [16][136] fp16 features
    __half* x2h = (__half*)bufA + 2048;     // [16][136] fp16 layer output (byte 4096)

    if (half_ == 1) {
        // ---- warp 1: load features -> fp16 into xh [16][136] ----
        const float4* xg = (const float4*)(feature + (size_t)g * NN * FIN);
        for (int i = lane; i < NN*32; i += 32) {
            int n = i >> 5, k4 = i & 31;
            float4 v = xg[i];
            __half2 lo = __halves2half2(__float2half_rn(v.x), __float2half_rn(v.y));
            __half2 hi = __halves2half2(__float2half_rn(v.z), __float2half_rn(v.w));
            *(uint2*)&xh[n*136 + k4*4] = make_uint2(*(uint*)&lo, *(uint*)&hi);
        }
        for (int i = lane; i < 2*136; i += 32) xh[14*136 + i] = __float2half_rn(0.f);
    } else {
        // ---- warp 0: counting sort of edges by dst (self-loops appended) ----
        if (lane < NN) cnt[lane] = 0;
        __syncwarp();
        for (int e = lane; e < NE; e += 32) {
            int d;
            if (e < E) {
                size_t base = ((size_t)g * E + e) * 2;
                d = is64 ? (int)((const long long*)eraw)[base + 1] : eraw[base + 1];
            } else d = e - E;
            atomicAdd(&cnt[d], 1);
        }
        __syncwarp();
        if (lane == 0) {
            int s = 0;
            #pragma unroll
            for (int i = 0; i < NN; i++) { off[i] = s; s += cnt[i]; cnt[i] = off[i]; }
            off[NN] = s;
        }
        __syncwarp();
        for (int e = lane; e < NE; e += 32) {
            int s, d;
            if (e < E) {
                size_t base = ((size_t)g * E + e) * 2;
                if (is64) { const long long* p = (const long long*)eraw;
                            s = (int)p[base]; d = (int)p[base + 1]; }
                else      { s = eraw[base];   d = eraw[base + 1]; }
            } else { s = d = e - E; }
            int pos = atomicAdd(&cnt[d], 1);
            srcS[pos] = (unsigned char)s;
        }
    }
    __syncthreads();

    gat_layer<8, true >(g_W1h, g_af1, b1v, xh,  bufA, h1_sm, x2h,
                        M_w, alj, srcS, off, t, lane, half_);
    gat_layer<4, false>(g_W2h, g_af2, b2v, x2h, bufA, h1_sm, x2h,
                        M_w, alj, srcS, off, t, lane, half_);

    // ---- fused head: sigmoid(flat . w_fused + b_fused) ----
    float p = 0.f;
    for (int i = t; i < NN*NC; i += 64) {
        int n = i >> 6, c = i & 63;
        p = fmaf(__half2float(x2h[n*136 + c]), g_wfused[i], p);
    }
    #pragma unroll
    for (int o = 16; o; o >>= 1) p += __shfl_xor_sync(0xffffffffu, p, o);
    if (lane == 0) red[half_] = p;
    __syncthreads();
    if (t == 0) {
        float s = g_bfused + red[0] + red[1];
        out[g] = 1.f / (1.f + __expf(-s));
    }
}

extern "C" void kernel_launch(void* const* d_in, const int* in_sizes, int n_in,
                              void* d_out, int out_size)
{
    const float* feature = (const float*)d_in[0];
    const int*   edges   = (const int*)  d_in[1];
    const float* W1   = (const float*)d_in[2];
    const float* as1  = (const float*)d_in[3];
    const float* ad1  = (const float*)d_in[4];
    const float* b1   = (const float*)d_in[5];
    const float* W2   = (const float*)d_in[6];
    const float* as2  = (const float*)d_in[7];
    const float* ad2  = (const float*)d_in[8];
    const float* b2   = (const float*)d_in[9];
    const float* Wlin = (const float*)d_in[10];
    const float* blin = (const float*)d_in[11];
    const float* Wpred= (const float*)d_in[12];
    const float* bpred= (const float*)d_in[13];

    int B = in_sizes[0] / (NN * FIN);       // 16384
    int E = in_sizes[1] / (2 * B);          // 182

    prep_kernel<<<48, 256>>>(W1, as1, ad1, W2, as2, ad2,
                             Wlin, blin, Wpred, bpred, edges);
    gat_kernel<<<B, 64>>>(feature, edges, b1, b2, (float*)d_out, E);
}